// round 1
// baseline (speedup 1.0000x reference)
#include <cuda_runtime.h>
#include <math.h>

#define S_LEN 128
#define BATCH 32
#define HID   1024
#define G4    4096
#define VOCAB 32000
#define MROWS (S_LEN*BATCH)   // 4096

#define CH     128
#define WS_ST  1028
#define HS_ST  132
#define LCTAS  128

// ---------------- scratch (static device allocations; no cudaMalloc) -------
__device__ float g_pre[(size_t)MROWS * G4];   // 64 MB: precomputed x @ w_ih^T
__device__ float g_hs[(size_t)MROWS * HID];   // 16 MB: h history (also decode A)
__device__ unsigned g_arrive = 0;
__device__ unsigned g_fini   = 0;

__device__ __forceinline__ float sigf(float x) { return 1.0f / (1.0f + __expf(-x)); }

// ======================================================================
// SGEMM NT: C[M,N] = A[M,K] * B[N,K]^T (+ bias). 128x128 tile, BK=8,
// 256 threads, 8x8 per-thread microtile.
// ======================================================================
__global__ void __launch_bounds__(256, 2) sgemm_nt(
    const float* __restrict__ A, const float* __restrict__ Bw,
    const float* __restrict__ bias, float* __restrict__ C,
    int N, int K)
{
    __shared__ float As[8][132];
    __shared__ float Bs[8][132];
    const int tid = threadIdx.x;
    const int m0 = blockIdx.x * 128;
    const int n0 = blockIdx.y * 128;
    const int lr = tid >> 1;
    const int lk = (tid & 1) << 2;
    const float* Ap = A  + (size_t)(m0 + lr) * K + lk;
    const float* Bp = Bw + (size_t)(n0 + lr) * K + lk;
    const int tm = (tid >> 4) << 3;
    const int tn = (tid & 15) << 3;

    float acc[8][8] = {};
    float4 av = *(const float4*)Ap;
    float4 bv = *(const float4*)Bp;

    for (int k0 = 0; k0 < K; k0 += 8) {
        __syncthreads();
        As[lk+0][lr]=av.x; As[lk+1][lr]=av.y; As[lk+2][lr]=av.z; As[lk+3][lr]=av.w;
        Bs[lk+0][lr]=bv.x; Bs[lk+1][lr]=bv.y; Bs[lk+2][lr]=bv.z; Bs[lk+3][lr]=bv.w;
        __syncthreads();
        if (k0 + 8 < K) {
            av = *(const float4*)(Ap + k0 + 8);
            bv = *(const float4*)(Bp + k0 + 8);
        }
        #pragma unroll
        for (int kk = 0; kk < 8; kk++) {
            float a[8], b[8];
            *(float4*)(a)   = *(const float4*)(&As[kk][tm]);
            *(float4*)(a+4) = *(const float4*)(&As[kk][tm+4]);
            *(float4*)(b)   = *(const float4*)(&Bs[kk][tn]);
            *(float4*)(b+4) = *(const float4*)(&Bs[kk][tn+4]);
            #pragma unroll
            for (int i = 0; i < 8; i++)
                #pragma unroll
                for (int j = 0; j < 8; j++)
                    acc[i][j] = fmaf(a[i], b[j], acc[i][j]);
        }
    }

    float bb[8];
    #pragma unroll
    for (int j = 0; j < 8; j++) bb[j] = bias ? bias[n0 + tn + j] : 0.0f;
    #pragma unroll
    for (int i = 0; i < 8; i++) {
        float* Crow = C + (size_t)(m0 + tm + i) * N + (n0 + tn);
        float4 o0, o1;
        o0.x = acc[i][0] + bb[0]; o0.y = acc[i][1] + bb[1];
        o0.z = acc[i][2] + bb[2]; o0.w = acc[i][3] + bb[3];
        o1.x = acc[i][4] + bb[4]; o1.y = acc[i][5] + bb[5];
        o1.z = acc[i][6] + bb[6]; o1.w = acc[i][7] + bb[7];
        *(float4*)(Crow)     = o0;
        *(float4*)(Crow + 4) = o1;
    }
}

// ======================================================================
// Same SGEMM but A rows gathered via token ids: A[m,:] = emb[idx[m],:]
// ======================================================================
__global__ void __launch_bounds__(256, 2) sgemm_nt_gather(
    const int* __restrict__ idx, const float* __restrict__ emb,
    const float* __restrict__ Bw, float* __restrict__ C,
    int N, int K)
{
    __shared__ float As[8][132];
    __shared__ float Bs[8][132];
    const int tid = threadIdx.x;
    const int m0 = blockIdx.x * 128;
    const int n0 = blockIdx.y * 128;
    const int lr = tid >> 1;
    const int lk = (tid & 1) << 2;
    const int tok = idx[m0 + lr];
    const float* Ap = emb + (size_t)tok * K + lk;
    const float* Bp = Bw  + (size_t)(n0 + lr) * K + lk;
    const int tm = (tid >> 4) << 3;
    const int tn = (tid & 15) << 3;

    float acc[8][8] = {};
    float4 av = *(const float4*)Ap;
    float4 bv = *(const float4*)Bp;

    for (int k0 = 0; k0 < K; k0 += 8) {
        __syncthreads();
        As[lk+0][lr]=av.x; As[lk+1][lr]=av.y; As[lk+2][lr]=av.z; As[lk+3][lr]=av.w;
        Bs[lk+0][lr]=bv.x; Bs[lk+1][lr]=bv.y; Bs[lk+2][lr]=bv.z; Bs[lk+3][lr]=bv.w;
        __syncthreads();
        if (k0 + 8 < K) {
            av = *(const float4*)(Ap + k0 + 8);
            bv = *(const float4*)(Bp + k0 + 8);
        }
        #pragma unroll
        for (int kk = 0; kk < 8; kk++) {
            float a[8], b[8];
            *(float4*)(a)   = *(const float4*)(&As[kk][tm]);
            *(float4*)(a+4) = *(const float4*)(&As[kk][tm+4]);
            *(float4*)(b)   = *(const float4*)(&Bs[kk][tn]);
            *(float4*)(b+4) = *(const float4*)(&Bs[kk][tn+4]);
            #pragma unroll
            for (int i = 0; i < 8; i++)
                #pragma unroll
                for (int j = 0; j < 8; j++)
                    acc[i][j] = fmaf(a[i], b[j], acc[i][j]);
        }
    }

    #pragma unroll
    for (int i = 0; i < 8; i++) {
        float* Crow = C + (size_t)(m0 + tm + i) * N + (n0 + tn);
        float4 o0, o1;
        o0.x = acc[i][0]; o0.y = acc[i][1]; o0.z = acc[i][2]; o0.w = acc[i][3];
        o1.x = acc[i][4]; o1.y = acc[i][5]; o1.z = acc[i][6]; o1.w = acc[i][7];
        *(float4*)(Crow)     = o0;
        *(float4*)(Crow + 4) = o1;
    }
}

// ======================================================================
// Persistent LSTM scan. 128 CTAs, 256 threads. CTA k owns h columns
// [8k, 8k+8) and the 4 gate rows of each (32 w_hh rows, cached in SMEM
// for the whole scan). One grid sync per step. c-state in registers.
// Warp w handles batch rows 4w..4w+3; lane = gate-row index (gate = lane/8,
// col = lane%8).
// ======================================================================
__global__ void __launch_bounds__(256) lstm_kernel(
    const float* __restrict__ hidden, const float* __restrict__ w_hh)
{
    extern __shared__ float sm[];
    float* Ws = sm;                 // [32][WS_ST]
    float* Hs = sm + 32 * WS_ST;    // [32][HS_ST]
    const int tid  = threadIdx.x;
    const int lane = tid & 31;
    const int warp = tid >> 5;
    const int hc0  = blockIdx.x << 3;
    const int b0   = warp << 2;

    // cache this CTA's 32 w_hh rows in SMEM (reused for 128 steps)
    for (int i = tid; i < 32 * 256; i += 256) {
        int r = i >> 8;
        int q = (i & 255) << 2;
        int j = ((r >> 3) << 10) + hc0 + (r & 7);
        float4 v = *(const float4*)(w_hh + ((size_t)j << 10) + q);
        float* d = Ws + r * WS_ST + q;
        d[0] = v.x; d[1] = v.y; d[2] = v.z; d[3] = v.w;
    }
    // c0 = h0 (reference sets c = hidden)
    float c0 = 0.f, c1 = 0.f, c2 = 0.f, c3 = 0.f;
    if (lane < 8) {
        c0 = hidden[((b0+0) << 10) + hc0 + lane];
        c1 = hidden[((b0+1) << 10) + hc0 + lane];
        c2 = hidden[((b0+2) << 10) + hc0 + lane];
        c3 = hidden[((b0+3) << 10) + hc0 + lane];
    }
    __syncthreads();

    const int jg = ((lane >> 3) << 10) + hc0 + (lane & 7);

    for (int s = 0; s < S_LEN; s++) {
        const float* hprev = (s == 0) ? hidden : (g_hs + ((size_t)(s - 1) << 15));
        float a0 = 0.f, a1 = 0.f, a2 = 0.f, a3 = 0.f;

        for (int k0 = 0; k0 < HID; k0 += CH) {
            __syncthreads();
            // stage h chunk [32][CH]; __ldcg: written by other SMs this launch
            #pragma unroll
            for (int i = tid; i < 1024; i += 256) {
                int b = i >> 5;
                int q = (i & 31) << 2;
                float4 v = __ldcg((const float4*)(hprev + ((size_t)b << 10) + k0 + q));
                float* d = Hs + b * HS_ST + q;
                d[0] = v.x; d[1] = v.y; d[2] = v.z; d[3] = v.w;
            }
            __syncthreads();
            const float* wr  = Ws + lane * WS_ST + k0;
            const float* h0p = Hs + (b0 + 0) * HS_ST;
            const float* h1p = Hs + (b0 + 1) * HS_ST;
            const float* h2p = Hs + (b0 + 2) * HS_ST;
            const float* h3p = Hs + (b0 + 3) * HS_ST;
            #pragma unroll
            for (int k = 0; k < CH; k += 4) {
                float4 w4 = *(const float4*)(wr + k);
                float4 x0 = *(const float4*)(h0p + k);
                float4 x1 = *(const float4*)(h1p + k);
                float4 x2 = *(const float4*)(h2p + k);
                float4 x3 = *(const float4*)(h3p + k);
                a0 = fmaf(w4.x,x0.x,a0); a0 = fmaf(w4.y,x0.y,a0); a0 = fmaf(w4.z,x0.z,a0); a0 = fmaf(w4.w,x0.w,a0);
                a1 = fmaf(w4.x,x1.x,a1); a1 = fmaf(w4.y,x1.y,a1); a1 = fmaf(w4.z,x1.z,a1); a1 = fmaf(w4.w,x1.w,a1);
                a2 = fmaf(w4.x,x2.x,a2); a2 = fmaf(w4.y,x2.y,a2); a2 = fmaf(w4.z,x2.z,a2); a2 = fmaf(w4.w,x2.w,a2);
                a3 = fmaf(w4.x,x3.x,a3); a3 = fmaf(w4.y,x3.y,a3); a3 = fmaf(w4.z,x3.z,a3); a3 = fmaf(w4.w,x3.w,a3);
            }
        }
        // add precomputed input projection
        {
            const float* prep = g_pre + (((size_t)(s * BATCH + b0)) << 12) + jg;
            a0 += __ldcg(prep);
            a1 += __ldcg(prep + (1u << 12));
            a2 += __ldcg(prep + (2u << 12));
            a3 += __ldcg(prep + (3u << 12));
        }
        // gather f/g/o gates into the i-gate lanes (0..7)
        const int bs = lane & 7;
        float f0 = __shfl_sync(0xffffffffu, a0, bs + 8);
        float gg0= __shfl_sync(0xffffffffu, a0, bs + 16);
        float o0 = __shfl_sync(0xffffffffu, a0, bs + 24);
        float f1 = __shfl_sync(0xffffffffu, a1, bs + 8);
        float gg1= __shfl_sync(0xffffffffu, a1, bs + 16);
        float o1 = __shfl_sync(0xffffffffu, a1, bs + 24);
        float f2 = __shfl_sync(0xffffffffu, a2, bs + 8);
        float gg2= __shfl_sync(0xffffffffu, a2, bs + 16);
        float o2 = __shfl_sync(0xffffffffu, a2, bs + 24);
        float f3 = __shfl_sync(0xffffffffu, a3, bs + 8);
        float gg3= __shfl_sync(0xffffffffu, a3, bs + 16);
        float o3 = __shfl_sync(0xffffffffu, a3, bs + 24);

        if (lane < 8) {
            float hn0, hn1, hn2, hn3;
            { float iv=sigf(a0), fv=sigf(f0), gv=tanhf(gg0), ov=sigf(o0);
              c0 = fv*c0 + iv*gv; hn0 = ov*tanhf(c0); }
            { float iv=sigf(a1), fv=sigf(f1), gv=tanhf(gg1), ov=sigf(o1);
              c1 = fv*c1 + iv*gv; hn1 = ov*tanhf(c1); }
            { float iv=sigf(a2), fv=sigf(f2), gv=tanhf(gg2), ov=sigf(o2);
              c2 = fv*c2 + iv*gv; hn2 = ov*tanhf(c2); }
            { float iv=sigf(a3), fv=sigf(f3), gv=tanhf(gg3), ov=sigf(o3);
              c3 = fv*c3 + iv*gv; hn3 = ov*tanhf(c3); }
            float* ho = g_hs + ((size_t)s << 15) + hc0 + lane;
            ho[(b0+0) << 10] = hn0;
            ho[(b0+1) << 10] = hn1;
            ho[(b0+2) << 10] = hn2;
            ho[(b0+3) << 10] = hn3;
        }
        // ---- grid barrier (monotonic arrive count; one per step) ----
        __syncthreads();
        if (tid == 0) {
            __threadfence();
            atomicAdd(&g_arrive, 1u);
            const unsigned tgt = (unsigned)(s + 1) * LCTAS;
            while (*((volatile unsigned*)&g_arrive) < tgt) { }
            __threadfence();
        }
        __syncthreads();
    }
    // reset barrier state for next graph replay (last CTA out resets)
    if (tid == 0) {
        unsigned p = atomicAdd(&g_fini, 1u);
        if (p == LCTAS - 1u) { atomicExch(&g_arrive, 0u); atomicExch(&g_fini, 0u); }
    }
}

// h_final = hs[S-1]
__global__ void copy_tail(float* __restrict__ out)
{
    int i = blockIdx.x * blockDim.x + threadIdx.x;
    if (i < BATCH * HID)
        out[(size_t)MROWS * VOCAB + i] = g_hs[((size_t)(S_LEN - 1) << 15) + i];
}

// ======================================================================
extern "C" void kernel_launch(void* const* d_in, const int* in_sizes, int n_in,
                              void* d_out, int out_size)
{
    const int*   input  = (const int*)  d_in[0];
    const float* hidden = (const float*)d_in[1];
    const float* emb_w  = (const float*)d_in[2];
    const float* w_ih   = (const float*)d_in[3];
    const float* w_hh   = (const float*)d_in[4];
    const float* dec_w  = (const float*)d_in[5];
    const float* dec_b  = (const float*)d_in[6];
    float* out = (float*)d_out;

    float* gpre_ptr = nullptr;
    float* ghs_ptr  = nullptr;
    cudaGetSymbolAddress((void**)&gpre_ptr, g_pre);
    cudaGetSymbolAddress((void**)&ghs_ptr,  g_hs);

    // 1) gates_pre = emb_w[input] @ w_ih^T   [4096 x 4096]
    sgemm_nt_gather<<<dim3(MROWS / 128, G4 / 128), 256>>>(
        input, emb_w, w_ih, gpre_ptr, G4, HID);

    // 2) persistent LSTM scan (fills g_hs)
    const int smem_bytes = (32 * WS_ST + 32 * HS_ST) * (int)sizeof(float);
    cudaFuncSetAttribute(lstm_kernel,
                         cudaFuncAttributeMaxDynamicSharedMemorySize, smem_bytes);
    lstm_kernel<<<LCTAS, 256, smem_bytes>>>(hidden, w_hh);

    // 3) decoded = hs @ dec_w^T + dec_b   [4096 x 32000]
    //    grid.x = M tiles (fastest) so all 32 M-tiles share each dec_w tile in L2
    sgemm_nt<<<dim3(MROWS / 128, VOCAB / 128), 256>>>(
        ghs_ptr, dec_w, dec_b, out, VOCAB, HID);

    // 4) h_final
    if (out_size >= MROWS * VOCAB + BATCH * HID)
        copy_tail<<<32, 1024>>>(out);
}

// round 4
// speedup vs baseline: 1.6582x; 1.6582x over previous
#include <cuda_runtime.h>
#include <cuda_bf16.h>
#include <math.h>
#include <stdint.h>

#define S_LEN 128
#define BATCH 32
#define HID   1024
#define G4    4096
#define VOCAB 32000
#define MROWS (S_LEN*BATCH)   // 4096

#define CH     128
#define WS_ST  1028
#define HS_ST  132
#define LCTAS  128

// ---- bf16x3 HMMA GEMM config ----
#define BM 128
#define BN 128
#define BK 32
#define NITK (HID/BK)        // 32
#define TSTRIDE 40           // smem row stride in bf16 elems (80 B: LDSM conflict-free)
#define TILE_BYTES (BM*TSTRIDE*2)   // 10240
#define STAGE_BYTES (4*TILE_BYTES)  // Ahi,Alo,Bhi,Blo
#define SMEM_GEMM (2*STAGE_BYTES)   // 81920

// ---------------- scratch (static device allocations) ----------------------
__device__ float g_pre[(size_t)MROWS * G4];              // 64 MB
__device__ float g_hs[(size_t)MROWS * HID];              // 16 MB
__device__ __nv_bfloat16 g_Ahi[(size_t)MROWS * HID];     // 8 MB  (emb rows, then hs)
__device__ __nv_bfloat16 g_Alo[(size_t)MROWS * HID];     // 8 MB
__device__ __nv_bfloat16 g_Whi[(size_t)G4 * HID];        // 8 MB  (w_ih)
__device__ __nv_bfloat16 g_Wlo[(size_t)G4 * HID];        // 8 MB
__device__ __nv_bfloat16 g_Bhi[(size_t)VOCAB * HID];     // 64 MB (dec_w)
__device__ __nv_bfloat16 g_Blo[(size_t)VOCAB * HID];     // 64 MB
__device__ unsigned g_arrive = 0;
__device__ unsigned g_fini   = 0;

__device__ __forceinline__ float sigf(float x) { return 1.0f / (1.0f + __expf(-x)); }

__device__ __forceinline__ uint32_t smem_u32(const void* p) {
    uint32_t a;
    asm("{ .reg .u64 t; cvta.to.shared.u64 t, %1; cvt.u32.u64 %0, t; }" : "=r"(a) : "l"(p));
    return a;
}
__device__ __forceinline__ void cpasync16(uint32_t dst, const void* src) {
    asm volatile("cp.async.cg.shared.global [%0], [%1], 16;" :: "r"(dst), "l"(src));
}
__device__ __forceinline__ void ldsm_x4(uint32_t* r, uint32_t addr) {
    asm volatile("ldmatrix.sync.aligned.m8n8.x4.shared.b16 {%0,%1,%2,%3}, [%4];"
                 : "=r"(r[0]), "=r"(r[1]), "=r"(r[2]), "=r"(r[3]) : "r"(addr));
}
__device__ __forceinline__ void mma_bf16(float* d, const uint32_t* a, const uint32_t* b) {
    asm volatile(
        "mma.sync.aligned.m16n8k16.row.col.f32.bf16.bf16.f32 "
        "{%0,%1,%2,%3}, {%4,%5,%6,%7}, {%8,%9}, {%0,%1,%2,%3};"
        : "+f"(d[0]), "+f"(d[1]), "+f"(d[2]), "+f"(d[3])
        : "r"(a[0]), "r"(a[1]), "r"(a[2]), "r"(a[3]), "r"(b[0]), "r"(b[1]));
}

// ======================================================================
// bf16x3 GEMM: C[M,N] = Ahi*Bhi^T + Alo*Bhi^T + Ahi*Blo^T (+bias)
// A row-major [M,K=1024], B row-major [N,K], fp32 accumulators.
// ======================================================================
__global__ void __launch_bounds__(256) gemm_bf16x3(
    const __nv_bfloat16* __restrict__ Ahi, const __nv_bfloat16* __restrict__ Alo,
    const __nv_bfloat16* __restrict__ Bhi, const __nv_bfloat16* __restrict__ Blo,
    const float* __restrict__ bias, float* __restrict__ C, int N)
{
    extern __shared__ __align__(128) char smem[];
    const uint32_t sb = smem_u32(smem);
    const int tid = threadIdx.x;
    const int wid = tid >> 5;
    const int lane = tid & 31;
    const int m0 = blockIdx.x * BM;
    const int n0 = blockIdx.y * BN;
    const int wm = wid & 3;      // 4 warps along M (32 rows each)
    const int wn = wid >> 2;     // 2 warps along N (64 cols each)

    float acc[2][8][4];
    #pragma unroll
    for (int i = 0; i < 2; i++)
        #pragma unroll
        for (int j = 0; j < 8; j++)
            #pragma unroll
            for (int q = 0; q < 4; q++) acc[i][j][q] = 0.0f;

    const char* srcs[4] = {
        (const char*)(Ahi + (size_t)m0 * HID),
        (const char*)(Alo + (size_t)m0 * HID),
        (const char*)(Bhi + (size_t)n0 * HID),
        (const char*)(Blo + (size_t)n0 * HID) };

    auto load_stage = [&](int it, int st) {
        const int kb = it * BK * 2;               // byte offset along K
        const uint32_t base = sb + st * STAGE_BYTES;
        #pragma unroll
        for (int u = 0; u < 8; u++) {
            int unit = tid + u * 256;             // 0..2047
            int tile = unit >> 9;                 // 0..3
            int rem  = unit & 511;
            int row  = rem >> 2;                  // 0..127
            int ch   = rem & 3;                   // 0..3 (16B chunks)
            cpasync16(base + tile * TILE_BYTES + row * 80 + ch * 16,
                      srcs[tile] + (size_t)row * (HID * 2) + kb + ch * 16);
        }
        asm volatile("cp.async.commit_group;" ::: "memory");
    };

    load_stage(0, 0);
    load_stage(1, 1);

    // lane-derived ldmatrix addressing
    const int rA = lane & 15;                  // A row within m16
    const int cA = (lane >> 4) << 3;           // A k chunk (0/8)
    const int rB = (lane & 7) + ((lane >> 4) << 3);  // B row within n16
    const int cB = ((lane >> 3) & 1) << 3;     // B k chunk (0/8)

    for (int it = 0; it < NITK; it++) {
        const int st = it & 1;
        asm volatile("cp.async.wait_group 1;" ::: "memory");
        __syncthreads();
        const uint32_t base = sb + st * STAGE_BYTES;
        const uint32_t Ah = base;
        const uint32_t Al = base + TILE_BYTES;
        const uint32_t Bh = base + 2 * TILE_BYTES;
        const uint32_t Bl = base + 3 * TILE_BYTES;

        #pragma unroll
        for (int ks = 0; ks < 2; ks++) {
            const int kofs = ks * 16;
            uint32_t ah[2][4], bh[4][4];
            #pragma unroll
            for (int mi = 0; mi < 2; mi++)
                ldsm_x4(ah[mi], Ah + ((wm*32 + mi*16 + rA) * TSTRIDE + kofs + cA) * 2);
            #pragma unroll
            for (int nq = 0; nq < 4; nq++)
                ldsm_x4(bh[nq], Bh + ((wn*64 + nq*16 + rB) * TSTRIDE + kofs + cB) * 2);
            // pass 0: hi*hi
            #pragma unroll
            for (int mi = 0; mi < 2; mi++)
                #pragma unroll
                for (int ni = 0; ni < 8; ni++)
                    mma_bf16(acc[mi][ni], ah[mi], &bh[ni >> 1][(ni & 1) * 2]);
            // pass 1: lo*hi
            {
                uint32_t al[2][4];
                #pragma unroll
                for (int mi = 0; mi < 2; mi++)
                    ldsm_x4(al[mi], Al + ((wm*32 + mi*16 + rA) * TSTRIDE + kofs + cA) * 2);
                #pragma unroll
                for (int mi = 0; mi < 2; mi++)
                    #pragma unroll
                    for (int ni = 0; ni < 8; ni++)
                        mma_bf16(acc[mi][ni], al[mi], &bh[ni >> 1][(ni & 1) * 2]);
            }
            // pass 2: hi*lo
            {
                uint32_t bl[4][4];
                #pragma unroll
                for (int nq = 0; nq < 4; nq++)
                    ldsm_x4(bl[nq], Bl + ((wn*64 + nq*16 + rB) * TSTRIDE + kofs + cB) * 2);
                #pragma unroll
                for (int mi = 0; mi < 2; mi++)
                    #pragma unroll
                    for (int ni = 0; ni < 8; ni++)
                        mma_bf16(acc[mi][ni], ah[mi], &bl[ni >> 1][(ni & 1) * 2]);
            }
        }
        __syncthreads();
        if (it + 2 < NITK) load_stage(it + 2, st);
        else asm volatile("cp.async.commit_group;" ::: "memory");
    }

    // epilogue
    const int row0 = m0 + wm * 32 + (lane >> 2);
    const int col0 = n0 + wn * 64 + (lane & 3) * 2;
    #pragma unroll
    for (int mi = 0; mi < 2; mi++) {
        #pragma unroll
        for (int ni = 0; ni < 8; ni++) {
            const int r = row0 + mi * 16;
            const int c = col0 + ni * 8;
            float b0 = 0.f, b1 = 0.f;
            if (bias) { b0 = __ldg(bias + c); b1 = __ldg(bias + c + 1); }
            float2 v0, v1;
            v0.x = acc[mi][ni][0] + b0; v0.y = acc[mi][ni][1] + b1;
            v1.x = acc[mi][ni][2] + b0; v1.y = acc[mi][ni][3] + b1;
            *(float2*)(C + (size_t)r * N + c)       = v0;
            *(float2*)(C + (size_t)(r + 8) * N + c) = v1;
        }
    }
}

// ======================================================================
// fp32 -> (bf16 hi, bf16 lo) split (flat)
// ======================================================================
__global__ void split_bf16(const float* __restrict__ x,
                           __nv_bfloat16* __restrict__ hi,
                           __nv_bfloat16* __restrict__ lo, size_t n)
{
    size_t stride = (size_t)gridDim.x * blockDim.x * 4;
    for (size_t i = ((size_t)blockIdx.x * blockDim.x + threadIdx.x) * 4; i < n; i += stride) {
        float4 v = *(const float4*)(x + i);
        __nv_bfloat16 h0 = __float2bfloat16(v.x);
        __nv_bfloat16 h1 = __float2bfloat16(v.y);
        __nv_bfloat16 h2 = __float2bfloat16(v.z);
        __nv_bfloat16 h3 = __float2bfloat16(v.w);
        __nv_bfloat16 l0 = __float2bfloat16(v.x - __bfloat162float(h0));
        __nv_bfloat16 l1 = __float2bfloat16(v.y - __bfloat162float(h1));
        __nv_bfloat16 l2 = __float2bfloat16(v.z - __bfloat162float(h2));
        __nv_bfloat16 l3 = __float2bfloat16(v.w - __bfloat162float(h3));
        uint2 H, L;
        H.x = ((uint32_t)__bfloat16_as_ushort(h1) << 16) | __bfloat16_as_ushort(h0);
        H.y = ((uint32_t)__bfloat16_as_ushort(h3) << 16) | __bfloat16_as_ushort(h2);
        L.x = ((uint32_t)__bfloat16_as_ushort(l1) << 16) | __bfloat16_as_ushort(l0);
        L.y = ((uint32_t)__bfloat16_as_ushort(l3) << 16) | __bfloat16_as_ushort(l2);
        *(uint2*)(hi + i) = H;
        *(uint2*)(lo + i) = L;
    }
}

// gather emb rows by token id and split to bf16 hi/lo. One block per row.
__global__ void gather_split_emb(const int* __restrict__ idx,
                                 const float* __restrict__ emb,
                                 __nv_bfloat16* __restrict__ hi,
                                 __nv_bfloat16* __restrict__ lo)
{
    const int m = blockIdx.x;
    const int tok = idx[m];
    const float4* src = (const float4*)(emb + (size_t)tok * HID);
    const int t = threadIdx.x;          // 256 threads, 256 float4s
    float4 v = __ldg(src + t);
    __nv_bfloat16 h0 = __float2bfloat16(v.x);
    __nv_bfloat16 h1 = __float2bfloat16(v.y);
    __nv_bfloat16 h2 = __float2bfloat16(v.z);
    __nv_bfloat16 h3 = __float2bfloat16(v.w);
    __nv_bfloat16 l0 = __float2bfloat16(v.x - __bfloat162float(h0));
    __nv_bfloat16 l1 = __float2bfloat16(v.y - __bfloat162float(h1));
    __nv_bfloat16 l2 = __float2bfloat16(v.z - __bfloat162float(h2));
    __nv_bfloat16 l3 = __float2bfloat16(v.w - __bfloat162float(h3));
    uint2 H, L;
    H.x = ((uint32_t)__bfloat16_as_ushort(h1) << 16) | __bfloat16_as_ushort(h0);
    H.y = ((uint32_t)__bfloat16_as_ushort(h3) << 16) | __bfloat16_as_ushort(h2);
    L.x = ((uint32_t)__bfloat16_as_ushort(l1) << 16) | __bfloat16_as_ushort(l0);
    L.y = ((uint32_t)__bfloat16_as_ushort(l3) << 16) | __bfloat16_as_ushort(l2);
    *(uint2*)(hi + (size_t)m * HID + t * 4) = H;
    *(uint2*)(lo + (size_t)m * HID + t * 4) = L;
}

// ======================================================================
// Persistent LSTM scan -- unchanged (passed in R1, rel_err 4.5e-7)
// ======================================================================
__global__ void __launch_bounds__(256) lstm_kernel(
    const float* __restrict__ hidden, const float* __restrict__ w_hh)
{
    extern __shared__ float sm[];
    float* Ws = sm;
    float* Hs = sm + 32 * WS_ST;
    const int tid  = threadIdx.x;
    const int lane = tid & 31;
    const int warp = tid >> 5;
    const int hc0  = blockIdx.x << 3;
    const int b0   = warp << 2;

    for (int i = tid; i < 32 * 256; i += 256) {
        int r = i >> 8;
        int q = (i & 255) << 2;
        int j = ((r >> 3) << 10) + hc0 + (r & 7);
        float4 v = *(const float4*)(w_hh + ((size_t)j << 10) + q);
        float* d = Ws + r * WS_ST + q;
        d[0] = v.x; d[1] = v.y; d[2] = v.z; d[3] = v.w;
    }
    float c0 = 0.f, c1 = 0.f, c2 = 0.f, c3 = 0.f;
    if (lane < 8) {
        c0 = hidden[((b0+0) << 10) + hc0 + lane];
        c1 = hidden[((b0+1) << 10) + hc0 + lane];
        c2 = hidden[((b0+2) << 10) + hc0 + lane];
        c3 = hidden[((b0+3) << 10) + hc0 + lane];
    }
    __syncthreads();

    const int jg = ((lane >> 3) << 10) + hc0 + (lane & 7);

    for (int s = 0; s < S_LEN; s++) {
        const float* hprev = (s == 0) ? hidden : (g_hs + ((size_t)(s - 1) << 15));
        float a0 = 0.f, a1 = 0.f, a2 = 0.f, a3 = 0.f;

        for (int k0 = 0; k0 < HID; k0 += CH) {
            __syncthreads();
            #pragma unroll
            for (int i = tid; i < 1024; i += 256) {
                int b = i >> 5;
                int q = (i & 31) << 2;
                float4 v = __ldcg((const float4*)(hprev + ((size_t)b << 10) + k0 + q));
                float* d = Hs + b * HS_ST + q;
                d[0] = v.x; d[1] = v.y; d[2] = v.z; d[3] = v.w;
            }
            __syncthreads();
            const float* wr  = Ws + lane * WS_ST + k0;
            const float* h0p = Hs + (b0 + 0) * HS_ST;
            const float* h1p = Hs + (b0 + 1) * HS_ST;
            const float* h2p = Hs + (b0 + 2) * HS_ST;
            const float* h3p = Hs + (b0 + 3) * HS_ST;
            #pragma unroll
            for (int k = 0; k < CH; k += 4) {
                float4 w4 = *(const float4*)(wr + k);
                float4 x0 = *(const float4*)(h0p + k);
                float4 x1 = *(const float4*)(h1p + k);
                float4 x2 = *(const float4*)(h2p + k);
                float4 x3 = *(const float4*)(h3p + k);
                a0 = fmaf(w4.x,x0.x,a0); a0 = fmaf(w4.y,x0.y,a0); a0 = fmaf(w4.z,x0.z,a0); a0 = fmaf(w4.w,x0.w,a0);
                a1 = fmaf(w4.x,x1.x,a1); a1 = fmaf(w4.y,x1.y,a1); a1 = fmaf(w4.z,x1.z,a1); a1 = fmaf(w4.w,x1.w,a1);
                a2 = fmaf(w4.x,x2.x,a2); a2 = fmaf(w4.y,x2.y,a2); a2 = fmaf(w4.z,x2.z,a2); a2 = fmaf(w4.w,x2.w,a2);
                a3 = fmaf(w4.x,x3.x,a3); a3 = fmaf(w4.y,x3.y,a3); a3 = fmaf(w4.z,x3.z,a3); a3 = fmaf(w4.w,x3.w,a3);
            }
        }
        {
            const float* prep = g_pre + (((size_t)(s * BATCH + b0)) << 12) + jg;
            a0 += __ldcg(prep);
            a1 += __ldcg(prep + (1u << 12));
            a2 += __ldcg(prep + (2u << 12));
            a3 += __ldcg(prep + (3u << 12));
        }
        const int bs = lane & 7;
        float f0 = __shfl_sync(0xffffffffu, a0, bs + 8);
        float gg0= __shfl_sync(0xffffffffu, a0, bs + 16);
        float o0 = __shfl_sync(0xffffffffu, a0, bs + 24);
        float f1 = __shfl_sync(0xffffffffu, a1, bs + 8);
        float gg1= __shfl_sync(0xffffffffu, a1, bs + 16);
        float o1 = __shfl_sync(0xffffffffu, a1, bs + 24);
        float f2 = __shfl_sync(0xffffffffu, a2, bs + 8);
        float gg2= __shfl_sync(0xffffffffu, a2, bs + 16);
        float o2 = __shfl_sync(0xffffffffu, a2, bs + 24);
        float f3 = __shfl_sync(0xffffffffu, a3, bs + 8);
        float gg3= __shfl_sync(0xffffffffu, a3, bs + 16);
        float o3 = __shfl_sync(0xffffffffu, a3, bs + 24);

        if (lane < 8) {
            float hn0, hn1, hn2, hn3;
            { float iv=sigf(a0), fv=sigf(f0), gv=tanhf(gg0), ov=sigf(o0);
              c0 = fv*c0 + iv*gv; hn0 = ov*tanhf(c0); }
            { float iv=sigf(a1), fv=sigf(f1), gv=tanhf(gg1), ov=sigf(o1);
              c1 = fv*c1 + iv*gv; hn1 = ov*tanhf(c1); }
            { float iv=sigf(a2), fv=sigf(f2), gv=tanhf(gg2), ov=sigf(o2);
              c2 = fv*c2 + iv*gv; hn2 = ov*tanhf(c2); }
            { float iv=sigf(a3), fv=sigf(f3), gv=tanhf(gg3), ov=sigf(o3);
              c3 = fv*c3 + iv*gv; hn3 = ov*tanhf(c3); }
            float* ho = g_hs + ((size_t)s << 15) + hc0 + lane;
            ho[(b0+0) << 10] = hn0;
            ho[(b0+1) << 10] = hn1;
            ho[(b0+2) << 10] = hn2;
            ho[(b0+3) << 10] = hn3;
        }
        __syncthreads();
        if (tid == 0) {
            __threadfence();
            atomicAdd(&g_arrive, 1u);
            const unsigned tgt = (unsigned)(s + 1) * LCTAS;
            while (*((volatile unsigned*)&g_arrive) < tgt) { }
            __threadfence();
        }
        __syncthreads();
    }
    if (tid == 0) {
        unsigned p = atomicAdd(&g_fini, 1u);
        if (p == LCTAS - 1u) { atomicExch(&g_arrive, 0u); atomicExch(&g_fini, 0u); }
    }
}

// h_final = hs[S-1]
__global__ void copy_tail(float* __restrict__ out)
{
    int i = blockIdx.x * blockDim.x + threadIdx.x;
    if (i < BATCH * HID)
        out[(size_t)MROWS * VOCAB + i] = g_hs[((size_t)(S_LEN - 1) << 15) + i];
}

// ======================================================================
extern "C" void kernel_launch(void* const* d_in, const int* in_sizes, int n_in,
                              void* d_out, int out_size)
{
    const int*   input  = (const int*)  d_in[0];
    const float* hidden = (const float*)d_in[1];
    const float* emb_w  = (const float*)d_in[2];
    const float* w_ih   = (const float*)d_in[3];
    const float* w_hh   = (const float*)d_in[4];
    const float* dec_w  = (const float*)d_in[5];
    const float* dec_b  = (const float*)d_in[6];
    float* out = (float*)d_out;

    float *gpre_ptr, *ghs_ptr;
    __nv_bfloat16 *ahi, *alo, *whi, *wlo, *bhi, *blo;
    cudaGetSymbolAddress((void**)&gpre_ptr, g_pre);
    cudaGetSymbolAddress((void**)&ghs_ptr,  g_hs);
    cudaGetSymbolAddress((void**)&ahi, g_Ahi);
    cudaGetSymbolAddress((void**)&alo, g_Alo);
    cudaGetSymbolAddress((void**)&whi, g_Whi);
    cudaGetSymbolAddress((void**)&wlo, g_Wlo);
    cudaGetSymbolAddress((void**)&bhi, g_Bhi);
    cudaGetSymbolAddress((void**)&blo, g_Blo);

    cudaFuncSetAttribute(gemm_bf16x3,
                         cudaFuncAttributeMaxDynamicSharedMemorySize, SMEM_GEMM);

    // 1) A = emb_w[input] split to bf16 hi/lo; w_ih split
    gather_split_emb<<<MROWS, 256>>>(input, emb_w, ahi, alo);
    split_bf16<<<512, 256>>>(w_ih, whi, wlo, (size_t)G4 * HID);

    // 2) gates_pre = emb_gathered @ w_ih^T on tensor cores (bf16x3)
    gemm_bf16x3<<<dim3(MROWS / BM, G4 / BN), 256, SMEM_GEMM>>>(
        ahi, alo, whi, wlo, nullptr, gpre_ptr, G4);

    // 3) dec_w split (independent of scan)
    split_bf16<<<2048, 256>>>(dec_w, bhi, blo, (size_t)VOCAB * HID);

    // 4) persistent LSTM scan
    const int smem_scan = (32 * WS_ST + 32 * HS_ST) * (int)sizeof(float);
    cudaFuncSetAttribute(lstm_kernel,
                         cudaFuncAttributeMaxDynamicSharedMemorySize, smem_scan);
    lstm_kernel<<<LCTAS, 256, smem_scan>>>(hidden, w_hh);

    // 5) hs split (overwrites emb splits; precompute already consumed them)
    split_bf16<<<1024, 256>>>(ghs_ptr, ahi, alo, (size_t)MROWS * HID);

    // 6) decode on tensor cores (bf16x3)
    gemm_bf16x3<<<dim3(MROWS / BM, VOCAB / BN), 256, SMEM_GEMM>>>(
        ahi, alo, bhi, blo, dec_b, out, VOCAB);

    // 7) h_final
    if (out_size >= MROWS * VOCAB + BATCH * HID)
        copy_tail<<<32, 1024>>>(out);
}